// round 12
// baseline (speedup 1.0000x reference)
#include <cuda_runtime.h>
#include <cuda_bf16.h>

typedef unsigned int u32;
typedef unsigned short u16;
typedef unsigned long long u64;

#define BATCH 64
#define SEQ   1024
#define DM    128
#define DEVINL __device__ __forceinline__

// bf16 hi/lo split scratch, packed pairs as u32.
// Q layout: [row][16*tig + t]            (A-fragment order, LDG.128-able)
// K layout: [row][pos8(p)]               (B-fragment order, LDS.64-able)
// VT layout:[b][h][pos8 within row]      (B-fragment order)
__device__ u32 g_q_hi[BATCH*SEQ*64];
__device__ u32 g_q_lo[BATCH*SEQ*64];
__device__ u32 g_k_hi[BATCH*SEQ*64];
__device__ u32 g_k_lo[BATCH*SEQ*64];
__device__ u32 g_vt_hi[BATCH*DM*512];
__device__ u32 g_vt_lo[BATCH*DM*512];

// ---------------- helpers ----------------
DEVINL float tanh_fast(float x){
    float ax = fminf(fabsf(x), 20.0f);
    float e  = __expf(2.0f*ax);
    return copysignf(__fdividef(e-1.0f, e+1.0f), x);
}
DEVINL u32 bfpair(float e0, float e1){ u32 r; asm("cvt.rn.bf16x2.f32 %0, %1, %2;":"=r"(r):"f"(e1),"f"(e0)); return r; }
DEVINL float bflo_f(u32 p){ return __uint_as_float(p<<16); }
DEVINL float bfhi_f(u32 p){ return __uint_as_float(p & 0xFFFF0000u); }
DEVINL void split2(float e0, float e1, u32 &hi, u32 &lo){
    hi = bfpair(e0, e1);
    lo = bfpair(e0 - bflo_f(hi), e1 - bfhi_f(hi));
}
DEVINL void mma16816(float* c, u32 a0,u32 a1,u32 a2,u32 a3, u32 b0,u32 b1){
    asm volatile("mma.sync.aligned.m16n8k16.row.col.f32.bf16.bf16.f32 "
        "{%0,%1,%2,%3}, {%4,%5,%6,%7}, {%8,%9}, {%0,%1,%2,%3};"
        : "+f"(c[0]),"+f"(c[1]),"+f"(c[2]),"+f"(c[3])
        : "r"(a0),"r"(a1),"r"(a2),"r"(a3),"r"(b0),"r"(b1));
}
DEVINL u32 sm_u32(const void* p){ u32 a; asm("{ .reg .u64 t; cvta.to.shared.u64 t, %1; cvt.u32.u64 %0, t; }":"=r"(a):"l"(p)); return a; }
DEVINL void cp16(u32 dst, const void* src){
    asm volatile("cp.async.cg.shared.global [%0], [%1], 16;"::"r"(dst),"l"(src):"memory");
}
#define CP_COMMIT() asm volatile("cp.async.commit_group;":::"memory")
#define CP_WAIT1()  asm volatile("cp.async.wait_group 1;":::"memory")
#define CP_WAIT0()  asm volatile("cp.async.wait_group 0;":::"memory")

// B-fragment permutation: pair p -> storage position within its 8-group
DEVINL int pos8(int p){ return ((p>>3)<<3) + ((p&3)<<1) + ((p>>2)&1); }

// =====================================================================
// Fused tensorized projections (one CTA = 128 rows, reuse x for 3 W's).
// =====================================================================
#define PW_STRIDE 68      // u32
#define PW_HI     0
#define PW_LO     8704
#define P_SMEM_BYTES (17408*4)   // 69,632 (y_s transpose scratch: 128*130*4=66,560)

__global__ void __launch_bounds__(256, 1)
proj_tc_kernel(const float* __restrict__ x,
               const float* __restrict__ Wq, const float* __restrict__ bq,
               const float* __restrict__ Wk, const float* __restrict__ bk,
               const float* __restrict__ Wv, const float* __restrict__ bv)
{
    extern __shared__ char smc[];
    u32* ws_hi = (u32*)smc + PW_HI;
    u32* ws_lo = (u32*)smc + PW_LO;

    int tid = threadIdx.x, wid = tid>>5, lane = tid&31;
    int g = lane>>2, tig = lane&3;
    int r0 = blockIdx.x * 128;
    int b  = r0 >> 10;
    int rowg = wid*16 + g;
    long grow0 = (long)(r0 + rowg);

    // ---- x fragments (persist): rows rowg, rowg+8 ----
    u32 axh[2][16], axl[2][16];
    #pragma unroll
    for (int r2=0;r2<2;++r2){
        const float* xr = x + (grow0 + 8*r2)*DM;
        #pragma unroll
        for (int t=0;t<16;++t){
            float2 v = __ldg((const float2*)(xr + 8*t + 2*tig));
            split2(v.x, v.y, axh[r2][t], axl[r2][t]);
        }
    }

    #pragma unroll 1
    for (int sel=0; sel<3; ++sel){
        const float* W    = (sel==0)? Wq : (sel==1)? Wk : Wv;
        const float* bias = (sel==0)? bq : (sel==1)? bk : bv;

        __syncthreads();
        // W -> smem in B-fragment (pos8) order
        #pragma unroll
        for (int p2=0;p2<16;++p2){
            int i = tid + p2*256, row = i>>5, c4 = (i&31)*4;
            float4 wv = __ldg((const float4*)(W + (long)row*DM + c4));
            u32 h0,l0,h1,l1;
            split2(wv.x, wv.y, h0, l0);
            split2(wv.z, wv.w, h1, l1);
            int p = c4>>1;                       // even pair index
            ws_hi[row*PW_STRIDE + pos8(p)]   = h0;
            ws_hi[row*PW_STRIDE + pos8(p+1)] = h1;
            ws_lo[row*PW_STRIDE + pos8(p)]   = l0;
            ws_lo[row*PW_STRIDE + pos8(p+1)] = l1;
        }
        __syncthreads();

        float oc[16][4];
        #pragma unroll
        for (int n=0;n<16;++n){ oc[n][0]=0; oc[n][1]=0; oc[n][2]=0; oc[n][3]=0; }
        #pragma unroll
        for (int n=0;n<16;++n){
            int h = 8*n + g;
            #pragma unroll
            for (int ks=0;ks<8;++ks){
                uint2 bh = *(const uint2*)&ws_hi[h*PW_STRIDE + 8*ks + 2*tig];
                uint2 bl = *(const uint2*)&ws_lo[h*PW_STRIDE + 8*ks + 2*tig];
                mma16816(oc[n], axh[0][2*ks], axh[1][2*ks], axh[0][2*ks+1], axh[1][2*ks+1], bh.x, bh.y);
                mma16816(oc[n], axh[0][2*ks], axh[1][2*ks], axh[0][2*ks+1], axh[1][2*ks+1], bl.x, bl.y);
                mma16816(oc[n], axl[0][2*ks], axl[1][2*ks], axl[0][2*ks+1], axl[1][2*ks+1], bh.x, bh.y);
            }
        }

        if (sel == 0){
            // Q: pair p=4n+tig stored at row*64 + 16*tig + n  -> 4x uint4 per row
            u32 hq[2][16], lq[2][16];
            #pragma unroll
            for (int n=0;n<16;++n){
                float2 b2 = __ldg((const float2*)(bias + 8*n + 2*tig));
                split2(tanh_fast(oc[n][0]+b2.x), tanh_fast(oc[n][1]+b2.y), hq[0][n], lq[0][n]);
                split2(tanh_fast(oc[n][2]+b2.x), tanh_fast(oc[n][3]+b2.y), hq[1][n], lq[1][n]);
            }
            #pragma unroll
            for (int r2=0;r2<2;++r2){
                long base = (grow0 + 8*r2)*64 + 16*tig;
                #pragma unroll
                for (int t4=0;t4<4;++t4){
                    *(uint4*)&g_q_hi[base + 4*t4] = make_uint4(hq[r2][4*t4],hq[r2][4*t4+1],hq[r2][4*t4+2],hq[r2][4*t4+3]);
                    *(uint4*)&g_q_lo[base + 4*t4] = make_uint4(lq[r2][4*t4],lq[r2][4*t4+1],lq[r2][4*t4+2],lq[r2][4*t4+3]);
                }
            }
        } else if (sel == 1){
            // K: pair p=4n+tig -> pos 8*(n>>1) + 2*tig + (n&1)  -> u64 per group
            u32 hk[2][16], lk[2][16];
            #pragma unroll
            for (int n=0;n<16;++n){
                float2 b2 = __ldg((const float2*)(bias + 8*n + 2*tig));
                split2(tanh_fast(oc[n][0]+b2.x), tanh_fast(oc[n][1]+b2.y), hk[0][n], lk[0][n]);
                split2(tanh_fast(oc[n][2]+b2.x), tanh_fast(oc[n][3]+b2.y), hk[1][n], lk[1][n]);
            }
            #pragma unroll
            for (int r2=0;r2<2;++r2){
                long base = (grow0 + 8*r2)*64 + 2*tig;
                #pragma unroll
                for (int gk=0;gk<8;++gk){
                    *(u64*)&g_k_hi[base + 8*gk] = ((u64)hk[r2][2*gk+1]<<32) | hk[r2][2*gk];
                    *(u64*)&g_k_lo[base + 8*gk] = ((u64)lk[r2][2*gk+1]<<32) | lk[r2][2*gk];
                }
            }
        } else {
            // V: transpose through smem -> g_vt[b][h][pos8(pair)]
            __syncthreads();
            float* y_s = (float*)smc;    // [h][row], stride 130
            #pragma unroll
            for (int n=0;n<16;++n){
                float2 b2 = __ldg((const float2*)(bias + 8*n + 2*tig));
                int col = 8*n + 2*tig;
                y_s[(col  )*130 + rowg    ] = tanh_fast(oc[n][0] + b2.x);
                y_s[(col+1)*130 + rowg    ] = tanh_fast(oc[n][1] + b2.y);
                y_s[(col  )*130 + rowg + 8] = tanh_fast(oc[n][2] + b2.x);
                y_s[(col+1)*130 + rowg + 8] = tanh_fast(oc[n][3] + b2.y);
            }
            __syncthreads();
            int h = tid >> 1;
            int phalf = (tid & 1) * 32;
            long gbase = ((long)(b*DM + h))*512 + ((r0 & 1023) >> 1) + phalf;
            #pragma unroll
            for (int g3=0; g3<4; ++g3){
                u32 hp[8], lp[8];
                #pragma unroll
                for (int t=0;t<8;++t){
                    int pg = phalf + g3*8 + t;
                    float2 yy = *(const float2*)(y_s + h*130 + 2*pg);
                    split2(yy.x, yy.y, hp[t], lp[t]);
                }
                // permuted group order: {0,4,1,5, 2,6,3,7}
                *(uint4*)(g_vt_hi + gbase + g3*8    ) = make_uint4(hp[0],hp[4],hp[1],hp[5]);
                *(uint4*)(g_vt_hi + gbase + g3*8 + 4) = make_uint4(hp[2],hp[6],hp[3],hp[7]);
                *(uint4*)(g_vt_lo + gbase + g3*8    ) = make_uint4(lp[0],lp[4],lp[1],lp[5]);
                *(uint4*)(g_vt_lo + gbase + g3*8 + 4) = make_uint4(lp[2],lp[6],lp[3],lp[7]);
            }
        }
    }
}

// =====================================================================
// Attention (mma.sync bf16, 3-term split) + cp.async double buffering.
// =====================================================================
#define KS_STRIDE 68
#define VT_STRIDE 36
#define OF_KH 0
#define OF_KL 4352
#define OF_VH 8704
#define OF_VL 13312
#define OF_MS 17920
#define BUF_U32 26624
#define A_SMEM (2*BUF_U32*4)   // 212,992 B

__global__ void __launch_bounds__(256, 1)
attn_kernel(const int* __restrict__ mask, float* __restrict__ out)
{
    extern __shared__ char smc[];
    u32* smp = (u32*)smc;
    u32  sb  = sm_u32(smc);

    int tid = threadIdx.x, wid = tid>>5, lane = tid&31;
    int g = lane>>2, tig = lane&3;
    int b  = blockIdx.y;
    int q0 = blockIdx.x * 128;
    int rowg  = wid*16 + g;
    long grow0 = (long)(b*SEQ + q0 + rowg);

    const uint4* gk_h = (const uint4*)(g_k_hi + (long)(b*SEQ)*64);
    const uint4* gk_l = (const uint4*)(g_k_lo + (long)(b*SEQ)*64);
    const uint4* gv_h = (const uint4*)(g_vt_hi + (long)(b*DM)*512);
    const uint4* gv_l = (const uint4*)(g_vt_lo + (long)(b*DM)*512);
    const int*   mg   = mask + ((long)(b*SEQ + q0))*SEQ;

    // ---- Q-hi fragments persist; Q-lo reloaded per block (frees 64 regs) ----
    const uint4* q4h0 = (const uint4*)(g_q_hi + grow0*64     + 16*tig);
    const uint4* q4h1 = (const uint4*)(g_q_hi + (grow0+8)*64 + 16*tig);
    const uint4* q4l0 = (const uint4*)(g_q_lo + grow0*64     + 16*tig);
    const uint4* q4l1 = (const uint4*)(g_q_lo + (grow0+8)*64 + 16*tig);
    u32 aqh[2][16];
    #pragma unroll
    for (int t4=0;t4<4;++t4){
        uint4 v0 = __ldg(&q4h0[t4]);
        aqh[0][4*t4]=v0.x; aqh[0][4*t4+1]=v0.y; aqh[0][4*t4+2]=v0.z; aqh[0][4*t4+3]=v0.w;
        uint4 v1 = __ldg(&q4h1[t4]);
        aqh[1][4*t4]=v1.x; aqh[1][4*t4+1]=v1.y; aqh[1][4*t4+2]=v1.z; aqh[1][4*t4+3]=v1.w;
    }

    auto stage = [&](int jb, int bi){
        u32 base = sb + (u32)(bi*BUF_U32*4);
        int j0 = jb*64;
        #pragma unroll
        for (int p=0;p<4;++p){                 // K: 64 rows x 16 uint4 (hi+lo)
            int i = tid + p*256, row = i>>4, c4 = (i&15)*4;
            int gi = j0*16 + i;
            cp16(base + (OF_KH + row*KS_STRIDE + c4)*4, gk_h + gi);
            cp16(base + (OF_KL + row*KS_STRIDE + c4)*4, gk_l + gi);
        }
        #pragma unroll
        for (int p=0;p<4;++p){                 // V^T: 128 rows x 8 uint4 (hi+lo)
            int i = tid + p*256, row = i>>3, c4 = (i&7)*4;
            int src = row*128 + (j0>>3) + (c4>>2);
            cp16(base + (OF_VH + row*VT_STRIDE + c4)*4, gv_h + src);
            cp16(base + (OF_VL + row*VT_STRIDE + c4)*4, gv_l + src);
        }
        #pragma unroll
        for (int p=0;p<8;++p){                 // mask raw: 128 rows x 16 uint4
            int i = tid + p*256, row = i>>4, c16 = (i&15);
            cp16(base + (OF_MS + row*KS_STRIDE + c16*4)*4,
                 (const uint4*)(mg + (long)row*SEQ + j0) + c16);
        }
    };

    float oc[16][4];
    #pragma unroll
    for (int n=0;n<16;++n){ oc[n][0]=0; oc[n][1]=0; oc[n][2]=0; oc[n][3]=0; }
    float rs0 = 0.0f, rs1 = 0.0f;

    stage(0, 0); CP_COMMIT();

    for (int jb = 0; jb < 16; ++jb) {
        __syncthreads();
        if (jb < 15) { stage(jb+1, (jb+1)&1); CP_COMMIT(); CP_WAIT1(); }
        else         { CP_WAIT0(); }
        __syncthreads();

        u32* bp    = smp + (jb&1)*BUF_U32;
        u32* ks_hi = bp + OF_KH;
        u32* ks_lo = bp + OF_KL;
        u32* vs_hi = bp + OF_VH;
        u32* vs_lo = bp + OF_VL;
        const int* msB = (const int*)(bp + OF_MS);

        // reload Q-lo fragments (L1-hot after block 0)
        u32 aql[2][16];
        #pragma unroll
        for (int t4=0;t4<4;++t4){
            uint4 v0 = __ldg(&q4l0[t4]);
            aql[0][4*t4]=v0.x; aql[0][4*t4+1]=v0.y; aql[0][4*t4+2]=v0.z; aql[0][4*t4+3]=v0.w;
            uint4 v1 = __ldg(&q4l1[t4]);
            aql[1][4*t4]=v1.x; aql[1][4*t4+1]=v1.y; aql[1][4*t4+2]=v1.z; aql[1][4*t4+3]=v1.w;
        }

        // ---- QK: S(16x64 per warp), 3-term split, LDS.64 B-frags ----
        float sc[8][4];
        #pragma unroll
        for (int n=0;n<8;++n){ sc[n][0]=0; sc[n][1]=0; sc[n][2]=0; sc[n][3]=0; }
        #pragma unroll
        for (int n=0;n<8;++n){
            int key = 8*n + g;
            #pragma unroll
            for (int ks=0;ks<8;++ks){
                uint2 bh = *(const uint2*)&ks_hi[key*KS_STRIDE + 8*ks + 2*tig];
                uint2 bl = *(const uint2*)&ks_lo[key*KS_STRIDE + 8*ks + 2*tig];
                mma16816(sc[n], aqh[0][2*ks], aqh[1][2*ks], aqh[0][2*ks+1], aqh[1][2*ks+1], bh.x, bh.y);
                mma16816(sc[n], aqh[0][2*ks], aqh[1][2*ks], aqh[0][2*ks+1], aqh[1][2*ks+1], bl.x, bl.y);
                mma16816(sc[n], aql[0][2*ks], aql[1][2*ks], aql[0][2*ks+1], aql[1][2*ks+1], bh.x, bh.y);
            }
        }

        // ---- mask + exp ----
        const int* mrow0 = msB + rowg*KS_STRIDE;
        const int* mrow1 = mrow0 + 8*KS_STRIDE;
        #pragma unroll
        for (int n=0;n<8;++n){
            int col = 8*n + 2*tig;
            int2 ma  = *(const int2*)(mrow0 + col);
            int2 mb2 = *(const int2*)(mrow1 + col);
            float p0 = ma.x  ? __expf(sc[n][0]) : 0.0f;
            float p1 = ma.y  ? __expf(sc[n][1]) : 0.0f;
            float p2 = mb2.x ? __expf(sc[n][2]) : 0.0f;
            float p3 = mb2.y ? __expf(sc[n][3]) : 0.0f;
            rs0 += p0 + p1;  rs1 += p2 + p3;
            sc[n][0]=p0; sc[n][1]=p1; sc[n][2]=p2; sc[n][3]=p3;
        }

        // ---- PV: O(16x128) += P(16x64) . V^T ----
        #pragma unroll
        for (int ks=0;ks<4;++ks){
            u32 ah[4], al[4];
            split2(sc[2*ks  ][0], sc[2*ks  ][1], ah[0], al[0]);
            split2(sc[2*ks  ][2], sc[2*ks  ][3], ah[1], al[1]);
            split2(sc[2*ks+1][0], sc[2*ks+1][1], ah[2], al[2]);
            split2(sc[2*ks+1][2], sc[2*ks+1][3], ah[3], al[3]);
            #pragma unroll
            for (int n=0;n<16;++n){
                int h = 8*n + g;
                uint2 bh = *(const uint2*)&vs_hi[h*VT_STRIDE + 8*ks + 2*tig];
                uint2 bl = *(const uint2*)&vs_lo[h*VT_STRIDE + 8*ks + 2*tig];
                mma16816(oc[n], ah[0],ah[1],ah[2],ah[3], bh.x, bh.y);
                mma16816(oc[n], ah[0],ah[1],ah[2],ah[3], bl.x, bl.y);
                mma16816(oc[n], al[0],al[1],al[2],al[3], bh.x, bh.y);
            }
        }
    }

    // ---- row sums (quad reduce) + normalize + store ----
    rs0 += __shfl_xor_sync(0xFFFFFFFFu, rs0, 1);
    rs0 += __shfl_xor_sync(0xFFFFFFFFu, rs0, 2);
    rs1 += __shfl_xor_sync(0xFFFFFFFFu, rs1, 1);
    rs1 += __shfl_xor_sync(0xFFFFFFFFu, rs1, 2);
    float inv0 = __fdividef(1.0f, rs0);
    float inv1 = __fdividef(1.0f, rs1);

    float* o0 = out + grow0*DM;
    float* o1 = o0 + 8*DM;
    #pragma unroll
    for (int n=0;n<16;++n){
        int col = 8*n + 2*tig;
        *(float2*)(o0 + col) = make_float2(oc[n][0]*inv0, oc[n][1]*inv0);
        *(float2*)(o1 + col) = make_float2(oc[n][2]*inv1, oc[n][3]*inv1);
    }
}

// =====================================================================
extern "C" void kernel_launch(void* const* d_in, const int* in_sizes, int n_in,
                              void* d_out, int out_size)
{
    const float* x    = (const float*)d_in[0];
    const int*   mask = (const int*)  d_in[1];
    const float* Wv   = (const float*)d_in[2];
    const float* bv   = (const float*)d_in[3];
    const float* Wk   = (const float*)d_in[4];
    const float* bk   = (const float*)d_in[5];
    const float* Wq   = (const float*)d_in[6];
    const float* bq   = (const float*)d_in[7];
    float* out = (float*)d_out;

    cudaFuncSetAttribute(proj_tc_kernel, cudaFuncAttributeMaxDynamicSharedMemorySize, P_SMEM_BYTES);
    cudaFuncSetAttribute(attn_kernel,    cudaFuncAttributeMaxDynamicSharedMemorySize, A_SMEM);

    proj_tc_kernel<<<512, 256, P_SMEM_BYTES>>>(x, Wq, bq, Wk, bk, Wv, bv);
    attn_kernel<<<dim3(SEQ/128, BATCH), 256, A_SMEM>>>(mask, out);
}

// round 13
// speedup vs baseline: 1.1231x; 1.1231x over previous
#include <cuda_runtime.h>
#include <cuda_bf16.h>

typedef unsigned int u32;
typedef unsigned short u16;
typedef unsigned long long u64;

#define BATCH 64
#define SEQ   1024
#define DM    128
#define DEVINL __device__ __forceinline__

// bf16 hi/lo split scratch, packed pairs as u32 (low half = even index)
__device__ u32 g_q_hi[BATCH*SEQ*64];
__device__ u32 g_q_lo[BATCH*SEQ*64];
__device__ u32 g_k_hi[BATCH*SEQ*64];
__device__ u32 g_k_lo[BATCH*SEQ*64];
__device__ u32 g_vt_hi[BATCH*DM*512];   // [b][h][j/2]
__device__ u32 g_vt_lo[BATCH*DM*512];

// ---------------- helpers ----------------
DEVINL float tanh_fast(float x){
    float ax = fminf(fabsf(x), 20.0f);
    float e  = __expf(2.0f*ax);
    return copysignf(__fdividef(e-1.0f, e+1.0f), x);
}
DEVINL u32 bfpair(float e0, float e1){ u32 r; asm("cvt.rn.bf16x2.f32 %0, %1, %2;":"=r"(r):"f"(e1),"f"(e0)); return r; }
DEVINL float bflo_f(u32 p){ return __uint_as_float(p<<16); }
DEVINL float bfhi_f(u32 p){ return __uint_as_float(p & 0xFFFF0000u); }
DEVINL void split2(float e0, float e1, u32 &hi, u32 &lo){
    hi = bfpair(e0, e1);
    lo = bfpair(e0 - bflo_f(hi), e1 - bfhi_f(hi));
}
DEVINL void mma16816(float* c, u32 a0,u32 a1,u32 a2,u32 a3, u32 b0,u32 b1){
    asm volatile("mma.sync.aligned.m16n8k16.row.col.f32.bf16.bf16.f32 "
        "{%0,%1,%2,%3}, {%4,%5,%6,%7}, {%8,%9}, {%0,%1,%2,%3};"
        : "+f"(c[0]),"+f"(c[1]),"+f"(c[2]),"+f"(c[3])
        : "r"(a0),"r"(a1),"r"(a2),"r"(a3),"r"(b0),"r"(b1));
}
DEVINL u32 sm_u32(const void* p){ u32 a; asm("{ .reg .u64 t; cvta.to.shared.u64 t, %1; cvt.u32.u64 %0, t; }":"=r"(a):"l"(p)); return a; }
DEVINL void cp16(u32 dst, const void* src){
    asm volatile("cp.async.cg.shared.global [%0], [%1], 16;"::"r"(dst),"l"(src):"memory");
}
#define CP_COMMIT() asm volatile("cp.async.commit_group;":::"memory")
#define CP_WAIT0()  asm volatile("cp.async.wait_group 0;":::"memory")
DEVINL void barh(int half){ asm volatile("bar.sync %0, %1;"::"r"(half+1),"r"(128):"memory"); }

// =====================================================================
// Fused tensorized projections (R11 version, verbatim): one CTA = 128
// rows; x fragments split once in registers, reused for Wq, Wk, Wv.
// =====================================================================
#define PW_STRIDE 68      // u32
#define PW_HI     0
#define PW_LO     8704
#define P_SMEM_BYTES (17408*4)   // 69,632 (y_s transpose scratch: 128*130*4=66,560)

__global__ void __launch_bounds__(256, 1)
proj_tc_kernel(const float* __restrict__ x,
               const float* __restrict__ Wq, const float* __restrict__ bq,
               const float* __restrict__ Wk, const float* __restrict__ bk,
               const float* __restrict__ Wv, const float* __restrict__ bv)
{
    extern __shared__ char smc[];
    u32* ws_hi = (u32*)smc + PW_HI;
    u32* ws_lo = (u32*)smc + PW_LO;

    int tid = threadIdx.x, wid = tid>>5, lane = tid&31;
    int g = lane>>2, tig = lane&3;
    int r0 = blockIdx.x * 128;
    int b  = r0 >> 10;
    int rowg = wid*16 + g;
    long grow0 = (long)(r0 + rowg);

    // ---- x fragments: rows rowg, rowg+8; split in registers, persist ----
    u32 axh[2][16], axl[2][16];
    #pragma unroll
    for (int r2=0;r2<2;++r2){
        const float* xr = x + (grow0 + 8*r2)*DM;
        #pragma unroll
        for (int t=0;t<16;++t){
            float2 v = __ldg((const float2*)(xr + 8*t + 2*tig));
            split2(v.x, v.y, axh[r2][t], axl[r2][t]);
        }
    }

    #pragma unroll 1
    for (int sel=0; sel<3; ++sel){
        const float* W    = (sel==0)? Wq : (sel==1)? Wk : Wv;
        const float* bias = (sel==0)? bq : (sel==1)? bk : bv;

        __syncthreads();   // prior sel done reading ws
        #pragma unroll
        for (int p=0;p<16;++p){
            int i = tid + p*256, row = i>>5, c4 = (i&31)*4;
            float4 wv = __ldg((const float4*)(W + (long)row*DM + c4));
            u32 h0,l0,h1,l1;
            split2(wv.x, wv.y, h0, l0);
            split2(wv.z, wv.w, h1, l1);
            *(u64*)(ws_hi + row*PW_STRIDE + (c4>>1)) = ((u64)h1<<32)|h0;
            *(u64*)(ws_lo + row*PW_STRIDE + (c4>>1)) = ((u64)l1<<32)|l0;
        }
        __syncthreads();

        float oc[16][4];
        #pragma unroll
        for (int n=0;n<16;++n){ oc[n][0]=0; oc[n][1]=0; oc[n][2]=0; oc[n][3]=0; }
        #pragma unroll
        for (int n=0;n<16;++n){
            int h = 8*n + g;
            #pragma unroll
            for (int ks=0;ks<8;++ks){
                u32 bh0 = ws_hi[h*PW_STRIDE + 8*ks + tig];
                u32 bh1 = ws_hi[h*PW_STRIDE + 8*ks + 4 + tig];
                u32 bl0 = ws_lo[h*PW_STRIDE + 8*ks + tig];
                u32 bl1 = ws_lo[h*PW_STRIDE + 8*ks + 4 + tig];
                mma16816(oc[n], axh[0][2*ks], axh[1][2*ks], axh[0][2*ks+1], axh[1][2*ks+1], bh0, bh1);
                mma16816(oc[n], axh[0][2*ks], axh[1][2*ks], axh[0][2*ks+1], axh[1][2*ks+1], bl0, bl1);
                mma16816(oc[n], axl[0][2*ks], axl[1][2*ks], axl[0][2*ks+1], axl[1][2*ks+1], bh0, bh1);
            }
        }

        if (sel < 2){
            u32* gh = (sel==0)? g_q_hi : g_k_hi;
            u32* gl = (sel==0)? g_q_lo : g_k_lo;
            #pragma unroll
            for (int n=0;n<16;++n){
                float2 b2 = __ldg((const float2*)(bias + 8*n + 2*tig));
                float y0 = tanh_fast(oc[n][0] + b2.x);
                float y1 = tanh_fast(oc[n][1] + b2.y);
                float y2 = tanh_fast(oc[n][2] + b2.x);
                float y3 = tanh_fast(oc[n][3] + b2.y);
                u32 h2,l2;
                split2(y0,y1,h2,l2);
                gh[grow0*64 + 4*n + tig] = h2;  gl[grow0*64 + 4*n + tig] = l2;
                split2(y2,y3,h2,l2);
                gh[(grow0+8)*64 + 4*n + tig] = h2;  gl[(grow0+8)*64 + 4*n + tig] = l2;
            }
        } else {
            // V: transpose through smem -> g_vt[b][h][j/2]
            __syncthreads();   // all warps done reading ws (about to overwrite)
            float* y_s = (float*)smc;    // [h][row], stride 130
            #pragma unroll
            for (int n=0;n<16;++n){
                float2 b2 = __ldg((const float2*)(bias + 8*n + 2*tig));
                int col = 8*n + 2*tig;
                y_s[(col  )*130 + rowg    ] = tanh_fast(oc[n][0] + b2.x);
                y_s[(col+1)*130 + rowg    ] = tanh_fast(oc[n][1] + b2.y);
                y_s[(col  )*130 + rowg + 8] = tanh_fast(oc[n][2] + b2.x);
                y_s[(col+1)*130 + rowg + 8] = tanh_fast(oc[n][3] + b2.y);
            }
            __syncthreads();
            int h = tid >> 1;
            int phalf = (tid & 1) * 32;
            long gbase = ((long)(b*DM + h))*512 + ((r0 & 1023) >> 1) + phalf;
            #pragma unroll
            for (int ck=0; ck<8; ++ck){
                u32 hw[4], lw[4];
                #pragma unroll
                for (int q2=0;q2<4;++q2){
                    int p2 = phalf + ck*4 + q2;
                    float2 yy = *(const float2*)(y_s + h*130 + 2*p2);
                    split2(yy.x, yy.y, hw[q2], lw[q2]);
                }
                *(uint4*)(g_vt_hi + gbase + ck*4) = make_uint4(hw[0],hw[1],hw[2],hw[3]);
                *(uint4*)(g_vt_lo + gbase + ck*4) = make_uint4(lw[0],lw[1],lw[2],lw[3]);
            }
        }
    }
}

// =====================================================================
// Attention: R11 inner math, restructured as TWO independent 128-thread
// pipelines per CTA (warps 0-3: rows 0-63; warps 4-7: rows 64-127),
// each with its own single buffer + named barrier. One half's MMAs
// cover the other half's staging latency (anti-phased on each SMSP).
// =====================================================================
#define KS_STRIDE 68
#define VT_STRIDE 36
// per-half u32 offsets
#define HOF_KH 0
#define HOF_KL 4352
#define HOF_VH 8704
#define HOF_VL 13312
#define HOF_MS 17920      // 64 rows * 68
#define HBUF_U32 22272
#define A_SMEM (2*HBUF_U32*4)   // 178,176 B

__global__ void __launch_bounds__(256, 1)
attn_kernel(const int* __restrict__ mask, float* __restrict__ out)
{
    extern __shared__ char smc[];
    u32  sb  = sm_u32(smc);

    int tid = threadIdx.x, wid = tid>>5, lane = tid&31;
    int g = lane>>2, tig = lane&3;
    int half = wid >> 2;           // 0 or 1
    int tidh = tid & 127;          // thread id within half
    int b  = blockIdx.y;
    int q0 = blockIdx.x * 128;
    int rowh  = half*64;                   // half's row base within CTA
    int rowg  = (wid&3)*16 + g;            // row within half (0..63)
    long grow0 = (long)(b*SEQ + q0 + rowh + rowg);

    u32* hb    = (u32*)smc + half*HBUF_U32;
    u32  hbb   = sb + (u32)(half*HBUF_U32*4);
    u32* ks_hi = hb + HOF_KH;
    u32* ks_lo = hb + HOF_KL;
    u32* vs_hi = hb + HOF_VH;
    u32* vs_lo = hb + HOF_VL;
    const int* msB = (const int*)(hb + HOF_MS);

    const uint4* gk_h = (const uint4*)(g_k_hi + (long)(b*SEQ)*64);
    const uint4* gk_l = (const uint4*)(g_k_lo + (long)(b*SEQ)*64);
    const uint4* gv_h = (const uint4*)(g_vt_hi + (long)(b*DM)*512);
    const uint4* gv_l = (const uint4*)(g_vt_lo + (long)(b*DM)*512);
    const int*   mg   = mask + ((long)(b*SEQ + q0 + rowh))*SEQ;   // half's 64 mask rows

    // ---- Q fragments (persist): rows rowg, rowg+8 of this half ----
    u32 aqh[2][16], aql[2][16];
    {
        const u32* qh0 = g_q_hi + grow0*64;
        const u32* ql0 = g_q_lo + grow0*64;
        #pragma unroll
        for (int t=0;t<16;++t){
            int c = 4*t + tig;
            aqh[0][t] = __ldg(&qh0[c]);  aqh[1][t] = __ldg(&qh0[8*64 + c]);
            aql[0][t] = __ldg(&ql0[c]);  aql[1][t] = __ldg(&ql0[8*64 + c]);
        }
    }

    // ---- per-half staging (128 threads) ----
    auto stage = [&](int jb){
        int j0 = jb*64;
        #pragma unroll
        for (int p=0;p<8;++p){                 // K: 64 rows x 16 uint4 (hi+lo)
            int i = tidh + p*128, row = i>>4, c4 = (i&15)*4;
            int gi = j0*16 + i;
            cp16(hbb + (HOF_KH + row*KS_STRIDE + c4)*4, gk_h + gi);
            cp16(hbb + (HOF_KL + row*KS_STRIDE + c4)*4, gk_l + gi);
        }
        #pragma unroll
        for (int p=0;p<8;++p){                 // V^T: 128 rows x 8 uint4 (hi+lo)
            int i = tidh + p*128, row = i>>3, c4 = (i&7)*4;
            int src = row*128 + (j0>>3) + (c4>>2);
            cp16(hbb + (HOF_VH + row*VT_STRIDE + c4)*4, gv_h + src);
            cp16(hbb + (HOF_VL + row*VT_STRIDE + c4)*4, gv_l + src);
        }
        #pragma unroll
        for (int p=0;p<8;++p){                 // mask: 64 rows x 16 uint4
            int i = tidh + p*128, row = i>>4, c16 = (i&15);
            cp16(hbb + (HOF_MS + row*KS_STRIDE + c16*4)*4,
                 (const uint4*)(mg + (long)row*SEQ + j0) + c16);
        }
    };

    float oc[16][4];
    #pragma unroll
    for (int n=0;n<16;++n){ oc[n][0]=0; oc[n][1]=0; oc[n][2]=0; oc[n][3]=0; }
    float rs0 = 0.0f, rs1 = 0.0f;

    stage(0); CP_COMMIT();

    for (int jb = 0; jb < 16; ++jb) {
        CP_WAIT0();
        barh(half);                            // half's buffer fully staged

        // ---- QK: S(16x64 per warp), 3-term split (R11 indices) ----
        float sc[8][4];
        #pragma unroll
        for (int n=0;n<8;++n){ sc[n][0]=0; sc[n][1]=0; sc[n][2]=0; sc[n][3]=0; }
        #pragma unroll
        for (int n=0;n<8;++n){
            int key = 8*n + g;
            #pragma unroll
            for (int ks=0;ks<8;++ks){
                u32 bh0 = ks_hi[key*KS_STRIDE + 8*ks + tig];
                u32 bh1 = ks_hi[key*KS_STRIDE + 8*ks + 4 + tig];
                u32 bl0 = ks_lo[key*KS_STRIDE + 8*ks + tig];
                u32 bl1 = ks_lo[key*KS_STRIDE + 8*ks + 4 + tig];
                mma16816(sc[n], aqh[0][2*ks], aqh[1][2*ks], aqh[0][2*ks+1], aqh[1][2*ks+1], bh0, bh1);
                mma16816(sc[n], aqh[0][2*ks], aqh[1][2*ks], aqh[0][2*ks+1], aqh[1][2*ks+1], bl0, bl1);
                mma16816(sc[n], aql[0][2*ks], aql[1][2*ks], aql[0][2*ks+1], aql[1][2*ks+1], bh0, bh1);
            }
        }

        // ---- mask + exp ----
        const int* mrow0 = msB + rowg*KS_STRIDE;
        const int* mrow1 = mrow0 + 8*KS_STRIDE;
        #pragma unroll
        for (int n=0;n<8;++n){
            int col = 8*n + 2*tig;
            int2 ma  = *(const int2*)(mrow0 + col);
            int2 mb2 = *(const int2*)(mrow1 + col);
            float p0 = ma.x  ? __expf(sc[n][0]) : 0.0f;
            float p1 = ma.y  ? __expf(sc[n][1]) : 0.0f;
            float p2 = mb2.x ? __expf(sc[n][2]) : 0.0f;
            float p3 = mb2.y ? __expf(sc[n][3]) : 0.0f;
            rs0 += p0 + p1;  rs1 += p2 + p3;
            sc[n][0]=p0; sc[n][1]=p1; sc[n][2]=p2; sc[n][3]=p3;
        }

        // ---- PV: O(16x128) += P(16x64) . V^T ----
        #pragma unroll
        for (int ks=0;ks<4;++ks){
            u32 ah[4], al[4];
            split2(sc[2*ks  ][0], sc[2*ks  ][1], ah[0], al[0]);
            split2(sc[2*ks  ][2], sc[2*ks  ][3], ah[1], al[1]);
            split2(sc[2*ks+1][0], sc[2*ks+1][1], ah[2], al[2]);
            split2(sc[2*ks+1][2], sc[2*ks+1][3], ah[3], al[3]);
            #pragma unroll
            for (int n=0;n<16;++n){
                int h = 8*n + g;
                u32 bh0 = vs_hi[h*VT_STRIDE + 8*ks + tig];
                u32 bh1 = vs_hi[h*VT_STRIDE + 8*ks + 4 + tig];
                u32 bl0 = vs_lo[h*VT_STRIDE + 8*ks + tig];
                u32 bl1 = vs_lo[h*VT_STRIDE + 8*ks + 4 + tig];
                mma16816(oc[n], ah[0],ah[1],ah[2],ah[3], bh0, bh1);
                mma16816(oc[n], ah[0],ah[1],ah[2],ah[3], bl0, bl1);
                mma16816(oc[n], al[0],al[1],al[2],al[3], bh0, bh1);
            }
        }

        barh(half);                            // half done reading buffer
        if (jb < 15) { stage(jb+1); CP_COMMIT(); }
    }

    // ---- row sums (quad reduce) + normalize + store ----
    rs0 += __shfl_xor_sync(0xFFFFFFFFu, rs0, 1);
    rs0 += __shfl_xor_sync(0xFFFFFFFFu, rs0, 2);
    rs1 += __shfl_xor_sync(0xFFFFFFFFu, rs1, 1);
    rs1 += __shfl_xor_sync(0xFFFFFFFFu, rs1, 2);
    float inv0 = __fdividef(1.0f, rs0);
    float inv1 = __fdividef(1.0f, rs1);

    float* o0 = out + grow0*DM;
    float* o1 = o0 + 8*DM;
    #pragma unroll
    for (int n=0;n<16;++n){
        int col = 8*n + 2*tig;
        *(float2*)(o0 + col) = make_float2(oc[n][0]*inv0, oc[n][1]*inv0);
        *(float2*)(o1 + col) = make_float2(oc[n][2]*inv1, oc[n][3]*inv1);
    }
}

// =====================================================================
extern "C" void kernel_launch(void* const* d_in, const int* in_sizes, int n_in,
                              void* d_out, int out_size)
{
    const float* x    = (const float*)d_in[0];
    const int*   mask = (const int*)  d_in[1];
    const float* Wv   = (const float*)d_in[2];
    const float* bv   = (const float*)d_in[3];
    const float* Wk   = (const float*)d_in[4];
    const float* bk   = (const float*)d_in[5];
    const float* Wq   = (const float*)d_in[6];
    const float* bq   = (const float*)d_in[7];
    float* out = (float*)d_out;

    cudaFuncSetAttribute(proj_tc_kernel, cudaFuncAttributeMaxDynamicSharedMemorySize, P_SMEM_BYTES);
    cudaFuncSetAttribute(attn_kernel,    cudaFuncAttributeMaxDynamicSharedMemorySize, A_SMEM);

    proj_tc_kernel<<<512, 256, P_SMEM_BYTES>>>(x, Wq, bq, Wk, bk, Wv, bv);
    attn_kernel<<<dim3(SEQ/128, BATCH), 256, A_SMEM>>>(mask, out);
}